// round 3
// baseline (speedup 1.0000x reference)
#include <cuda_runtime.h>
#include <cstdint>

// x: [2][4][8][8][8][96][96] f32, W: [9][4][4][3][3][3] f32, b: [9][4] f32
// out: [2][4][6][6][8][96][96] f32
#define HW_PLANE 9216
typedef unsigned long long u64;

__device__ __forceinline__ void cp_async16(uint32_t saddr, const void* g, int srcsize) {
    asm volatile("cp.async.cg.shared.global [%0], [%1], 16, %2;\n"
                 :: "r"(saddr), "l"(g), "r"(srcsize));
}
__device__ __forceinline__ void cp_commit() {
    asm volatile("cp.async.commit_group;\n" ::: "memory");
}
__device__ __forceinline__ void cp_wait1() {
    asm volatile("cp.async.wait_group 1;\n" ::: "memory");
}
__device__ __forceinline__ u64 pack2(float lo, float hi) {
    u64 r; asm("mov.b64 %0, {%1, %2};" : "=l"(r) : "f"(lo), "f"(hi)); return r;
}
__device__ __forceinline__ void ffma2(u64& a, u64 x, u64 w) {
    asm("fma.rn.f32x2 %0, %1, %2, %0;" : "+l"(a) : "l"(x), "l"(w));
}
__device__ __forceinline__ float2 unpack2(u64 v) {
    float lo, hi; asm("mov.b64 {%0, %1}, %2;" : "=f"(lo), "=f"(hi) : "l"(v));
    return make_float2(lo, hi);
}

// Block: 384 threads = 24 tx (4 cols) x 16 ty (2 rows). Tile 32 rows x 96 cols, 4 o-chans.
// 108 iters = ci(4) x ij(9) x kd(3). Triple-buffered planes, f32x2 FMAs, 3 blocks/SM.
__global__ __launch_bounds__(384, 3)
void conv5d_kernel(const float* __restrict__ x,
                   const float* __restrict__ Wg,
                   const float* __restrict__ bg,
                   float* __restrict__ out)
{
    __shared__ __align__(16) float wsh[3888];          // [n(108)][tap(9)][o(4)]
    __shared__ __align__(16) float tile[3][34 * 104];  // row: [pad3][w=-1][w0..95][w=96][pad3]
    __shared__ float mbsh[4];

    const int tid   = threadIdx.x;
    const int htile = blockIdx.x % 3;
    const int d     = blockIdx.x / 3;
    const int t     = blockIdx.y;
    const int c     = blockIdx.z % 6;
    const int b     = blockIdx.z / 6;
    const int h0    = htile * 32;

    // ---- stage weights: wsh[n*36 + tap*4 + o], n = (ci*9+ij)*3+kd
    for (int idx = tid; idx < 3888; idx += 384) {
        int o   = idx & 3;
        int tap = (idx >> 2) % 9;
        int kd  = (idx / 36) % 3;
        int ij  = (idx / 108) % 9;
        int ci  = idx / 972;
        int kh = tap / 3, kw = tap - kh * 3;
        wsh[idx] = Wg[((ij * 4 + o) * 4 + ci) * 27 + kd * 9 + kh * 3 + kw];
    }
    if (tid < 4) {
        float s = 0.f;
        #pragma unroll
        for (int ij = 0; ij < 9; ij++) s += bg[ij * 4 + tid];
        mbsh[tid] = s * (1.0f / 9.0f);
    }
    // halo columns (w=-1, w=96) are conv zero-padding: zero once, never loaded
    if (tid < 102) {  // 3 bufs x 34 rows
        int buf = tid / 34, row = tid - buf * 34;
        tile[buf][row * 104 + 3]   = 0.f;
        tile[buf][row * 104 + 100] = 0.f;
    }

    // ---- per-thread interior load slots (16B each): 34 rows x 24 quads = 816
    int   mso[3];     // smem float offset, -1 unused
    int   mgo[3];     // global plane offset
    int   msz[3];     // 16 if h valid else 0
    #pragma unroll
    for (int e = 0; e < 3; e++) {
        int idx = tid + e * 384;
        if (idx < 816) {
            int row = idx / 24;
            int q   = idx - row * 24;
            int h   = h0 - 1 + row;
            bool hv = (h >= 0 && h < 96);
            mso[e] = row * 104 + 4 + q * 4;
            mgo[e] = (hv ? h : 0) * 96 + q * 4;
            msz[e] = hv ? 16 : 0;
        } else {
            mso[e] = -1;
        }
    }

    uint32_t sb[3];
    sb[0] = (uint32_t)__cvta_generic_to_shared(tile[0]);
    sb[1] = (uint32_t)__cvta_generic_to_shared(tile[1]);
    sb[2] = (uint32_t)__cvta_generic_to_shared(tile[2]);

    // ---- issue-side state machine over (ci, i, j, kd)
    const float* xb = x + (size_t)b * (4 * 8 * 8 * 8 * HW_PLANE);
    const float* bcur = xb + ((size_t)((c * 8 + t) * 8) + (d - 1)) * HW_PLANE;
    int kd_m = 0, jj = 0, ii = 0;
    const bool dval0 = (d >= 1), dval2 = (d <= 6);

    auto issue_buf = [&](uint32_t sbase) {
        bool dv = (kd_m == 0) ? dval0 : ((kd_m == 2) ? dval2 : true);
        const float* plane = dv ? (bcur + (size_t)kd_m * HW_PLANE) : (bcur + HW_PLANE);
        #pragma unroll
        for (int e = 0; e < 3; e++) {
            if (mso[e] >= 0)
                cp_async16(sbase + (uint32_t)mso[e] * 4u, plane + mgo[e], dv ? msz[e] : 0);
        }
        kd_m++;
        if (kd_m == 3) {
            kd_m = 0;
            long step = 8;                      // j++
            jj++;
            if (jj == 3) { jj = 0; ii++; step = 48;          // i++
                if (ii == 3) { ii = 0; step = 368; } }       // ci++
            bcur += step * (long)HW_PLANE;
        }
    };

    // accumulators: (o0,o1) and (o2,o3) pairs, [py][px]
    u64 a01[2][4], a23[2][4];
    #pragma unroll
    for (int py = 0; py < 2; py++)
        #pragma unroll
        for (int px = 0; px < 4; px++) { a01[py][px] = 0ull; a23[py][px] = 0ull; }

    issue_buf(sb[0]); cp_commit();
    issue_buf(sb[1]); cp_commit();

    const int tx = tid % 24;
    const int ty = tid / 24;
    const int rowbase = ty * 2 * 104 + tx * 4;

    #pragma unroll 3
    for (int n = 0; n < 108; n++) {
        cp_wait1();              // group n complete
        __syncthreads();         // visible to all; prev compute done
        if (n < 106) issue_buf(sb[(n + 2) % 3]);
        cp_commit();

        const float* tb = &tile[n % 3][rowbase];
        const ulonglong2* wb2 = reinterpret_cast<const ulonglong2*>(&wsh[n * 36]);

        // row-streaming: load one input row, apply to both output rows it feeds
        #pragma unroll
        for (int rr = 0; rr < 4; rr++) {
            const float* rw = tb + rr * 104;
            float  lv = rw[3];
            float4 m  = *reinterpret_cast<const float4*>(rw + 4);
            float  rv = rw[8];
            u64 p[6];
            p[0] = pack2(lv,  lv);
            p[1] = pack2(m.x, m.x);
            p[2] = pack2(m.y, m.y);
            p[3] = pack2(m.z, m.z);
            p[4] = pack2(m.w, m.w);
            p[5] = pack2(rv,  rv);

            if (rr < 3) {        // py = 0, kh = rr
                #pragma unroll
                for (int kw = 0; kw < 3; kw++) {
                    ulonglong2 w2 = wb2[rr * 3 + kw];
                    #pragma unroll
                    for (int px = 0; px < 4; px++) {
                        ffma2(a01[0][px], p[kw + px], w2.x);
                        ffma2(a23[0][px], p[kw + px], w2.y);
                    }
                }
            }
            if (rr >= 1) {       // py = 1, kh = rr - 1
                #pragma unroll
                for (int kw = 0; kw < 3; kw++) {
                    ulonglong2 w2 = wb2[(rr - 1) * 3 + kw];
                    #pragma unroll
                    for (int px = 0; px < 4; px++) {
                        ffma2(a01[1][px], p[kw + px], w2.x);
                        ffma2(a23[1][px], p[kw + px], w2.y);
                    }
                }
            }
        }
    }

    // ---- epilogue
    const float invn = 1.0f / 9.0f;
    size_t ob = ((((size_t)(b * 4) * 6 + c) * 6 + t) * 8 + d) * (size_t)HW_PLANE;
    const size_t ostride = (size_t)6 * 6 * 8 * HW_PLANE;

    #pragma unroll
    for (int py = 0; py < 2; py++) {
        int h = h0 + ty * 2 + py;
        size_t rowoff = ob + (size_t)h * 96 + tx * 4;
        float v0[4], v1[4], v2[4], v3[4];
        #pragma unroll
        for (int px = 0; px < 4; px++) {
            float2 p01 = unpack2(a01[py][px]);
            float2 p23 = unpack2(a23[py][px]);
            v0[px] = p01.x; v1[px] = p01.y; v2[px] = p23.x; v3[px] = p23.y;
        }
        float4 w4;
        w4 = make_float4(fmaf(v0[0], invn, mbsh[0]), fmaf(v0[1], invn, mbsh[0]),
                         fmaf(v0[2], invn, mbsh[0]), fmaf(v0[3], invn, mbsh[0]));
        *reinterpret_cast<float4*>(out + rowoff) = w4;
        w4 = make_float4(fmaf(v1[0], invn, mbsh[1]), fmaf(v1[1], invn, mbsh[1]),
                         fmaf(v1[2], invn, mbsh[1]), fmaf(v1[3], invn, mbsh[1]));
        *reinterpret_cast<float4*>(out + rowoff + ostride) = w4;
        w4 = make_float4(fmaf(v2[0], invn, mbsh[2]), fmaf(v2[1], invn, mbsh[2]),
                         fmaf(v2[2], invn, mbsh[2]), fmaf(v2[3], invn, mbsh[2]));
        *reinterpret_cast<float4*>(out + rowoff + 2 * ostride) = w4;
        w4 = make_float4(fmaf(v3[0], invn, mbsh[3]), fmaf(v3[1], invn, mbsh[3]),
                         fmaf(v3[2], invn, mbsh[3]), fmaf(v3[3], invn, mbsh[3]));
        *reinterpret_cast<float4*>(out + rowoff + 3 * ostride) = w4;
    }
}

extern "C" void kernel_launch(void* const* d_in, const int* in_sizes, int n_in,
                              void* d_out, int out_size) {
    const float* x  = (const float*)d_in[0];
    const float* Wg = (const float*)d_in[1];
    const float* bg = (const float*)d_in[2];
    float* out = (float*)d_out;

    dim3 grid(24, 6, 12);   // x: htile(3) + 3*d(8); y: t(6); z: b*6+c(12)
    dim3 block(384);
    conv5d_kernel<<<grid, block>>>(x, Wg, bg, out);
}

// round 4
// speedup vs baseline: 1.2080x; 1.2080x over previous
#include <cuda_runtime.h>
#include <cstdint>

// x: [2][4][8][8][8][96][96] f32, W: [9][4][4][3][3][3] f32, b: [9][4] f32
// out: [2][4][6][6][8][96][96] f32
#define HW_PLANE 9216
#define TSTRIDE  104            // floats per tile row
#define TSZ      (34 * TSTRIDE) // floats per buffer
typedef unsigned long long u64;

__device__ __forceinline__ void cp_async16(uint32_t saddr, const void* g, int srcsize) {
    asm volatile("cp.async.cg.shared.global [%0], [%1], 16, %2;\n"
                 :: "r"(saddr), "l"(g), "r"(srcsize));
}
__device__ __forceinline__ void cp_commit() {
    asm volatile("cp.async.commit_group;\n" ::: "memory");
}
__device__ __forceinline__ void cp_wait2() {
    asm volatile("cp.async.wait_group 2;\n" ::: "memory");
}
__device__ __forceinline__ u64 pack2(float lo, float hi) {
    u64 r; asm("mov.b64 %0, {%1, %2};" : "=l"(r) : "f"(lo), "f"(hi)); return r;
}
__device__ __forceinline__ void ffma2(u64& a, u64 x, u64 w) {
    asm("fma.rn.f32x2 %0, %1, %2, %0;" : "+l"(a) : "l"(x), "l"(w));
}
__device__ __forceinline__ float2 unpack2(u64 v) {
    float lo, hi; asm("mov.b64 {%0, %1}, %2;" : "=f"(lo), "=f"(hi) : "l"(v));
    return make_float2(lo, hi);
}

// Block: 384 threads = 24 tx (4 cols) x 16 ty (2 rows). Tile 32 rows x 96 cols, 4 o-chans.
// 108 iters = ci(4) x ij(9) x kd(3). 6 smem buffers (dynamic), 2 iters per barrier,
// 4 cp.async groups in flight, f32x2-packed FMAs. 2 blocks/SM.
__global__ __launch_bounds__(384, 2)
void conv5d_kernel(const float* __restrict__ x,
                   const float* __restrict__ Wg,
                   const float* __restrict__ bg,
                   float* __restrict__ out)
{
    extern __shared__ __align__(16) float tiles[];     // [6][TSZ]
    __shared__ __align__(16) float wsh[3888];          // [n(108)][tap(9)][o(4)]
    __shared__ float mbsh[4];

    const int tid   = threadIdx.x;
    const int htile = blockIdx.x % 3;
    const int d     = blockIdx.x / 3;
    const int t     = blockIdx.y;
    const int c     = blockIdx.z % 6;
    const int b     = blockIdx.z / 6;
    const int h0    = htile * 32;

    // ---- stage weights: wsh[n*36 + tap*4 + o], n = (ci*9+ij)*3+kd
    for (int idx = tid; idx < 3888; idx += 384) {
        int o   = idx & 3;
        int tap = (idx >> 2) % 9;
        int kd  = (idx / 36) % 3;
        int ij  = (idx / 108) % 9;
        int ci  = idx / 972;
        int kh = tap / 3, kw = tap - kh * 3;
        wsh[idx] = Wg[((ij * 4 + o) * 4 + ci) * 27 + kd * 9 + kh * 3 + kw];
    }
    if (tid < 4) {
        float s = 0.f;
        #pragma unroll
        for (int ij = 0; ij < 9; ij++) s += bg[ij * 4 + tid];
        mbsh[tid] = s * (1.0f / 9.0f);
    }
    // halo columns (w=-1, w=96) are conv zero-padding: zero once, never loaded
    if (tid < 204) {  // 6 bufs x 34 rows
        int buf = tid / 34, row = tid - buf * 34;
        tiles[buf * TSZ + row * TSTRIDE + 3]   = 0.f;
        tiles[buf * TSZ + row * TSTRIDE + 100] = 0.f;
    }

    // ---- per-thread interior load slots (16B each): 34 rows x 24 quads = 816
    int   mso[3];     // smem float offset, -1 unused
    int   mgo[3];     // global plane offset
    int   msz[3];     // 16 if h valid else 0
    #pragma unroll
    for (int e = 0; e < 3; e++) {
        int idx = tid + e * 384;
        if (idx < 816) {
            int row = idx / 24;
            int q   = idx - row * 24;
            int h   = h0 - 1 + row;
            bool hv = (h >= 0 && h < 96);
            mso[e] = row * TSTRIDE + 4 + q * 4;
            mgo[e] = (hv ? h : 0) * 96 + q * 4;
            msz[e] = hv ? 16 : 0;
        } else {
            mso[e] = -1;
        }
    }

    uint32_t sb[6];
    #pragma unroll
    for (int k = 0; k < 6; k++)
        sb[k] = (uint32_t)__cvta_generic_to_shared(tiles + k * TSZ);

    // ---- issue-side state machine over (ci, i, j, kd)
    const float* xb = x + (size_t)b * (4 * 8 * 8 * 8 * HW_PLANE);
    const float* bcur = xb + ((size_t)((c * 8 + t) * 8) + (d - 1)) * HW_PLANE;
    int kd_m = 0, jj = 0, ii = 0;
    const bool dval0 = (d >= 1), dval2 = (d <= 6);

    auto issue_buf = [&](uint32_t sbase) {
        bool dv = (kd_m == 0) ? dval0 : ((kd_m == 2) ? dval2 : true);
        const float* plane = dv ? (bcur + (size_t)kd_m * HW_PLANE) : (bcur + HW_PLANE);
        #pragma unroll
        for (int e = 0; e < 3; e++) {
            if (mso[e] >= 0)
                cp_async16(sbase + (uint32_t)mso[e] * 4u, plane + mgo[e], dv ? msz[e] : 0);
        }
        kd_m++;
        if (kd_m == 3) {
            kd_m = 0;
            long step = 8;                      // j++
            jj++;
            if (jj == 3) { jj = 0; ii++; step = 48;          // i++
                if (ii == 3) { ii = 0; step = 368; } }       // ci++
            bcur += step * (long)HW_PLANE;
        }
    };

    // accumulators: (o0,o1) and (o2,o3) pairs, [py][px]
    u64 a01[2][4], a23[2][4];
    #pragma unroll
    for (int py = 0; py < 2; py++)
        #pragma unroll
        for (int px = 0; px < 4; px++) { a01[py][px] = 0ull; a23[py][px] = 0ull; }

    const int tx = tid % 24;
    const int ty = tid / 24;
    const int rowbase = ty * 2 * TSTRIDE + tx * 4;

    // R2-style compute for one iteration: weights once, 4 rows cached in regs
    auto compute = [&](int n, const float* tb) {
        const ulonglong2* wb = reinterpret_cast<const ulonglong2*>(&wsh[n * 36]);
        float4 wtmp;
        u64 rp[4][6];
        #pragma unroll
        for (int rr = 0; rr < 4; rr++) {
            const float* rw = tb + rr * TSTRIDE;
            float  lv = rw[3];
            float4 m  = *reinterpret_cast<const float4*>(rw + 4);
            float  rv = rw[8];
            rp[rr][0] = pack2(lv,  lv);
            rp[rr][1] = pack2(m.x, m.x);
            rp[rr][2] = pack2(m.y, m.y);
            rp[rr][3] = pack2(m.z, m.z);
            rp[rr][4] = pack2(m.w, m.w);
            rp[rr][5] = pack2(rv,  rv);
        }
        (void)wtmp;
        #pragma unroll
        for (int kh = 0; kh < 3; kh++)
            #pragma unroll
            for (int kw = 0; kw < 3; kw++) {
                ulonglong2 w2 = wb[kh * 3 + kw];
                #pragma unroll
                for (int py = 0; py < 2; py++)
                    #pragma unroll
                    for (int px = 0; px < 4; px++) {
                        u64 xv = rp[py + kh][kw + px];
                        ffma2(a01[py][px], xv, w2.x);
                        ffma2(a23[py][px], xv, w2.y);
                    }
            }
    };

    // prologue: 4 groups in flight
    issue_buf(sb[0]); cp_commit();
    issue_buf(sb[1]); cp_commit();
    issue_buf(sb[2]); cp_commit();
    issue_buf(sb[3]); cp_commit();

    // 54 phases x 2 iters; buffer pattern repeats every 3 phases -> unroll 3
    #pragma unroll 3
    for (int p = 0; p < 54; p++) {
        const int n0 = 2 * p;
        cp_wait2();              // all but 2 newest groups done -> iters n0, n0+1 arrived
        __syncthreads();         // visible to all; bufs (n0+4)%6,(n0+5)%6 no longer read

        if (n0 + 4 < 108) issue_buf(sb[(n0 + 4) % 6]);
        cp_commit();
        if (n0 + 5 < 108) issue_buf(sb[(n0 + 5) % 6]);
        cp_commit();

        compute(n0,     tiles + ((n0)     % 6) * TSZ + rowbase);
        compute(n0 + 1, tiles + ((n0 + 1) % 6) * TSZ + rowbase);
    }

    // ---- epilogue
    const float invn = 1.0f / 9.0f;
    size_t ob = ((((size_t)(b * 4) * 6 + c) * 6 + t) * 8 + d) * (size_t)HW_PLANE;
    const size_t ostride = (size_t)6 * 6 * 8 * HW_PLANE;

    #pragma unroll
    for (int py = 0; py < 2; py++) {
        int h = h0 + ty * 2 + py;
        size_t rowoff = ob + (size_t)h * 96 + tx * 4;
        float v0[4], v1[4], v2[4], v3[4];
        #pragma unroll
        for (int px = 0; px < 4; px++) {
            float2 p01 = unpack2(a01[py][px]);
            float2 p23 = unpack2(a23[py][px]);
            v0[px] = p01.x; v1[px] = p01.y; v2[px] = p23.x; v3[px] = p23.y;
        }
        float4 w4;
        w4 = make_float4(fmaf(v0[0], invn, mbsh[0]), fmaf(v0[1], invn, mbsh[0]),
                         fmaf(v0[2], invn, mbsh[0]), fmaf(v0[3], invn, mbsh[0]));
        *reinterpret_cast<float4*>(out + rowoff) = w4;
        w4 = make_float4(fmaf(v1[0], invn, mbsh[1]), fmaf(v1[1], invn, mbsh[1]),
                         fmaf(v1[2], invn, mbsh[1]), fmaf(v1[3], invn, mbsh[1]));
        *reinterpret_cast<float4*>(out + rowoff + ostride) = w4;
        w4 = make_float4(fmaf(v2[0], invn, mbsh[2]), fmaf(v2[1], invn, mbsh[2]),
                         fmaf(v2[2], invn, mbsh[2]), fmaf(v2[3], invn, mbsh[2]));
        *reinterpret_cast<float4*>(out + rowoff + 2 * ostride) = w4;
        w4 = make_float4(fmaf(v3[0], invn, mbsh[3]), fmaf(v3[1], invn, mbsh[3]),
                         fmaf(v3[2], invn, mbsh[3]), fmaf(v3[3], invn, mbsh[3]));
        *reinterpret_cast<float4*>(out + rowoff + 3 * ostride) = w4;
    }
}

extern "C" void kernel_launch(void* const* d_in, const int* in_sizes, int n_in,
                              void* d_out, int out_size) {
    const float* x  = (const float*)d_in[0];
    const float* Wg = (const float*)d_in[1];
    const float* bg = (const float*)d_in[2];
    float* out = (float*)d_out;

    const int dynsmem = 6 * TSZ * (int)sizeof(float);   // 6 input-plane buffers
    cudaFuncSetAttribute(conv5d_kernel, cudaFuncAttributeMaxDynamicSharedMemorySize, dynsmem);

    dim3 grid(24, 6, 12);   // x: htile(3) + 3*d(8); y: t(6); z: b*6+c(12)
    dim3 block(384);
    conv5d_kernel<<<grid, block, dynsmem>>>(x, Wg, bg, out);
}